// round 1
// baseline (speedup 1.0000x reference)
#include <cuda_runtime.h>
#include <math.h>

// ---------------------------------------------------------------------------
// SOMI settling layer, collapsed formulation.
//
// out = H @ h  (per (b,s) row over hidden dim), where
//   H = (1-gate) I + gate * F_10
//   F/G matrix recurrence replicates the 10-step semi-implicit Euler settle:
//     G' = dt*M*F + (1-dt*beta)*G + dt*diag(p)
//     F' = F + dt*G'
//   M  = alpha1*|W|/deg  - (alpha1 + alpha0 + p[e]) on the diagonal
//   deg[e] = max(sum_d |W[e,d]|, 1e-8)
// ---------------------------------------------------------------------------

#define DIM 512
#define N_STEPS 10

static constexpr float ALPHA_1F = 1.0f;
static constexpr float ALPHA_0F = 0.1f;
static constexpr float DTF      = 0.1f;
static constexpr float BETAF    = 2.8982753492378876f;  // 2*sqrt(2.1)

// Scratch (allocation-free rule: device globals)
__device__ __align__(16) float g_deg[DIM];
__device__ __align__(16) float g_M[DIM * DIM];
__device__ __align__(16) float g_F[2][DIM * DIM];
__device__ __align__(16) float g_G[2][DIM * DIM];
__device__ __align__(16) float g_H[DIM * DIM];

// ---------------------------------------------------------------------------
// deg[e] = max(sum_d |W[e,d]|, 1e-8)   — one warp per row
// ---------------------------------------------------------------------------
__global__ void build_deg(const float* __restrict__ W) {
    int warp = (blockIdx.x * blockDim.x + threadIdx.x) >> 5;
    int lane = threadIdx.x & 31;
    if (warp >= DIM) return;
    float s = 0.f;
    const float* row = W + (size_t)warp * DIM;
    for (int d = lane; d < DIM; d += 32) s += fabsf(row[d]);
    #pragma unroll
    for (int o = 16; o > 0; o >>= 1) s += __shfl_down_sync(0xffffffffu, s, o);
    if (lane == 0) g_deg[warp] = fmaxf(s, 1e-8f);
}

// ---------------------------------------------------------------------------
// M, F0 = I, G0 = 0
// ---------------------------------------------------------------------------
__global__ void build_M_init(const float* __restrict__ W,
                             const float* __restrict__ p) {
    int idx = blockIdx.x * blockDim.x + threadIdx.x;
    if (idx >= DIM * DIM) return;
    int e = idx >> 9;
    int d = idx & (DIM - 1);
    float m = ALPHA_1F * fabsf(W[idx]) / g_deg[e];
    float f0 = 0.f;
    if (e == d) {
        m -= (ALPHA_1F + ALPHA_0F + p[d]);
        f0 = 1.f;
    }
    g_M[idx] = m;
    g_F[0][idx] = f0;
    g_G[0][idx] = 0.f;
}

// ---------------------------------------------------------------------------
// One settle step on the matrices (fused GEMM + update, ping-pong buffers):
//   T = M @ F_src  (512x512x512)
//   G_dst = (1-dt*beta)*G_src + dt*T + dt*diag(p)
//   F_dst = F_src + dt*G_dst
// 64x64 tile, 256 threads, 4x4 per thread.
// ---------------------------------------------------------------------------
__global__ __launch_bounds__(256)
void step_gemm(int src, const float* __restrict__ p) {
    constexpr int BM = 64, BN = 64, BK = 16;
    __shared__ float Ms[BK][BM];
    __shared__ float Fs[BK][BN];

    const float* __restrict__ Fsrc = g_F[src];
    const float* __restrict__ Gsrc = g_G[src];
    float* __restrict__ Fdst = g_F[src ^ 1];
    float* __restrict__ Gdst = g_G[src ^ 1];

    const int tid  = threadIdx.x;
    const int brow = blockIdx.x * BM;
    const int bcol = blockIdx.y * BN;
    const int tx = tid & 15;   // 16 cols of threads
    const int ty = tid >> 4;   // 16 rows of threads

    float acc[4][4];
    #pragma unroll
    for (int i = 0; i < 4; i++)
        #pragma unroll
        for (int j = 0; j < 4; j++) acc[i][j] = 0.f;

    for (int k0 = 0; k0 < DIM; k0 += BK) {
        // Load M tile (BM x BK), transposed store into Ms[k][row]
        {
            int row = tid >> 2;          // 0..63
            int kq  = tid & 3;           // 0..3 (x4 floats)
            float4 v = *(const float4*)&g_M[(size_t)(brow + row) * DIM + k0 + kq * 4];
            Ms[kq * 4 + 0][row] = v.x;
            Ms[kq * 4 + 1][row] = v.y;
            Ms[kq * 4 + 2][row] = v.z;
            Ms[kq * 4 + 3][row] = v.w;
        }
        // Load F tile (BK x BN), natural layout
        {
            int krow = tid >> 4;         // 0..15
            int jq   = tid & 15;         // 0..15 (x4 floats)
            float4 v = *(const float4*)&Fsrc[(size_t)(k0 + krow) * DIM + bcol + jq * 4];
            *(float4*)&Fs[krow][jq * 4] = v;
        }
        __syncthreads();

        #pragma unroll
        for (int kk = 0; kk < BK; kk++) {
            float a[4], b[4];
            #pragma unroll
            for (int i = 0; i < 4; i++) a[i] = Ms[kk][ty * 4 + i];
            #pragma unroll
            for (int j = 0; j < 4; j++) b[j] = Fs[kk][tx * 4 + j];
            #pragma unroll
            for (int i = 0; i < 4; i++)
                #pragma unroll
                for (int j = 0; j < 4; j++)
                    acc[i][j] = fmaf(a[i], b[j], acc[i][j]);
        }
        __syncthreads();
    }

    const float c1 = 1.0f - DTF * BETAF;
    #pragma unroll
    for (int i = 0; i < 4; i++) {
        int gi = brow + ty * 4 + i;
        #pragma unroll
        for (int j = 0; j < 4; j++) {
            int gj = bcol + tx * 4 + j;
            int ij = gi * DIM + gj;
            float gn = c1 * Gsrc[ij] + DTF * acc[i][j];
            if (gi == gj) gn += DTF * p[gi];
            Gdst[ij] = gn;
            Fdst[ij] = Fsrc[ij] + DTF * gn;
        }
    }
}

// ---------------------------------------------------------------------------
// H = gate * F_final + (1-gate) * I
// ---------------------------------------------------------------------------
__global__ void finalize_H(const float* __restrict__ ga, int src) {
    int idx = blockIdx.x * blockDim.x + threadIdx.x;
    if (idx >= DIM * DIM) return;
    float gate = tanhf(ga[0]);
    int e = idx >> 9;
    int d = idx & (DIM - 1);
    float v = gate * g_F[src][idx];
    if (e == d) v += 1.0f - gate;
    g_H[idx] = v;
}

// ---------------------------------------------------------------------------
// out[r, e] = sum_d h[r, d] * H[e, d]      (R = B*S = 16384 rows)
// 128x128 tile, 256 threads, 8x8 per thread, BK=16. Both operands K-major (NT).
// ---------------------------------------------------------------------------
__global__ __launch_bounds__(256)
void big_gemm(const float* __restrict__ A, float* __restrict__ C, int R) {
    constexpr int BM = 128, BN = 128, BK = 16;
    __shared__ float As[BK][BM];
    __shared__ float Bs[BK][BN];

    const int tid  = threadIdx.x;
    const int brow = blockIdx.x * BM;
    const int bcol = blockIdx.y * BN;
    const int tx = tid & 15;
    const int ty = tid >> 4;

    float acc[8][8];
    #pragma unroll
    for (int i = 0; i < 8; i++)
        #pragma unroll
        for (int j = 0; j < 8; j++) acc[i][j] = 0.f;

    for (int k0 = 0; k0 < DIM; k0 += BK) {
        // Each operand tile: 128 rows x 16 K = 512 float4; 256 threads -> 2 each.
        #pragma unroll
        for (int t = 0; t < 2; t++) {
            int idx = tid + t * 256;
            int row = idx >> 2;      // 0..127
            int kq  = idx & 3;       // x4 floats
            float4 av = *(const float4*)&A[(size_t)(brow + row) * DIM + k0 + kq * 4];
            As[kq * 4 + 0][row] = av.x;
            As[kq * 4 + 1][row] = av.y;
            As[kq * 4 + 2][row] = av.z;
            As[kq * 4 + 3][row] = av.w;
            float4 bv = *(const float4*)&g_H[(size_t)(bcol + row) * DIM + k0 + kq * 4];
            Bs[kq * 4 + 0][row] = bv.x;
            Bs[kq * 4 + 1][row] = bv.y;
            Bs[kq * 4 + 2][row] = bv.z;
            Bs[kq * 4 + 3][row] = bv.w;
        }
        __syncthreads();

        #pragma unroll
        for (int kk = 0; kk < BK; kk++) {
            float a[8], b[8];
            #pragma unroll
            for (int i = 0; i < 8; i++) a[i] = As[kk][ty * 8 + i];
            #pragma unroll
            for (int j = 0; j < 8; j++) b[j] = Bs[kk][tx * 8 + j];
            #pragma unroll
            for (int i = 0; i < 8; i++)
                #pragma unroll
                for (int j = 0; j < 8; j++)
                    acc[i][j] = fmaf(a[i], b[j], acc[i][j]);
        }
        __syncthreads();
    }

    #pragma unroll
    for (int i = 0; i < 8; i++) {
        int r = brow + ty * 8 + i;
        float* crow = C + (size_t)r * DIM + bcol + tx * 8;
        float4 v0 = make_float4(acc[i][0], acc[i][1], acc[i][2], acc[i][3]);
        float4 v1 = make_float4(acc[i][4], acc[i][5], acc[i][6], acc[i][7]);
        *(float4*)(crow + 0) = v0;
        *(float4*)(crow + 4) = v1;
    }
}

// ---------------------------------------------------------------------------
extern "C" void kernel_launch(void* const* d_in, const int* in_sizes, int n_in,
                              void* d_out, int out_size) {
    const float* h  = (const float*)d_in[0];  // hidden_states [B,S,D]
    const float* W  = (const float*)d_in[1];  // [D,D]
    const float* ga = (const float*)d_in[2];  // gate_alpha [1]
    const float* p  = (const float*)d_in[3];  // precision [D]
    float* out = (float*)d_out;

    const int R = in_sizes[0] / DIM;          // B*S = 16384

    build_deg<<<(DIM * 32 + 255) / 256, 256>>>(W);
    build_M_init<<<(DIM * DIM + 255) / 256, 256>>>(W, p);

    int src = 0;
    for (int it = 0; it < N_STEPS; it++) {
        step_gemm<<<dim3(DIM / 64, DIM / 64), 256>>>(src, p);
        src ^= 1;
    }

    finalize_H<<<(DIM * DIM + 255) / 256, 256>>>(ga, src);

    big_gemm<<<dim3(R / 128, DIM / 128), 256>>>(h, out, R);
}

// round 2
// speedup vs baseline: 1.5839x; 1.5839x over previous
#include <cuda_runtime.h>
#include <math.h>

// ---------------------------------------------------------------------------
// SOMI settling layer, collapsed formulation.
//   out = H @ h,  H = (1-gate) I + gate * F_10
//   F/G matrix recurrence (10 semi-implicit Euler steps):
//     G' = dt*M*F + c1*G + dt*diag(p),  F' = F + dt*G',  c1 = 1 - dt*beta
//   M  = alpha1*|W|/deg - (alpha1+alpha0+p) on diag;  deg = max(row-sum |W|,1e-8)
//   Step 1 is analytic (F0 = I): G1 = dt*(M + diag(p)), F1 = I + dt*G1.
//   Remaining 9 steps: split-K GEMM (4 slabs) + fused combine epilogue.
// ---------------------------------------------------------------------------

#define DIM 512
#define KS  4           // split-K factor for step GEMMs
#define KCH (DIM / KS)  // 128

static constexpr float ALPHA_1F = 1.0f;
static constexpr float ALPHA_0F = 0.1f;
static constexpr float DTF      = 0.1f;
static constexpr float BETAF    = 2.8982753492378876f;  // 2*sqrt(2.1)
static constexpr float C1F      = 1.0f - DTF * BETAF;

// Scratch (allocation-free rule: device globals)
__device__ __align__(16) float g_deg[DIM];
__device__ __align__(16) float g_M[DIM * DIM];
__device__ __align__(16) float g_F[2][DIM * DIM];
__device__ __align__(16) float g_G[2][DIM * DIM];
__device__ __align__(16) float g_T[KS][DIM * DIM];
__device__ __align__(16) float g_H[DIM * DIM];

// ---------------------------------------------------------------------------
// deg[e] = max(sum_d |W[e,d]|, 1e-8)   — one warp per row
// ---------------------------------------------------------------------------
__global__ void build_deg(const float* __restrict__ W) {
    int warp = (blockIdx.x * blockDim.x + threadIdx.x) >> 5;
    int lane = threadIdx.x & 31;
    if (warp >= DIM) return;
    float s = 0.f;
    const float* row = W + (size_t)warp * DIM;
    for (int d = lane; d < DIM; d += 32) s += fabsf(row[d]);
    #pragma unroll
    for (int o = 16; o > 0; o >>= 1) s += __shfl_down_sync(0xffffffffu, s, o);
    if (lane == 0) g_deg[warp] = fmaxf(s, 1e-8f);
}

// ---------------------------------------------------------------------------
// Build M and analytic first step: G1 = dt*(M + diag(p)), F1 = I + dt*G1
// ---------------------------------------------------------------------------
__global__ void build_M_init(const float* __restrict__ W,
                             const float* __restrict__ p) {
    int idx = blockIdx.x * blockDim.x + threadIdx.x;
    if (idx >= DIM * DIM) return;
    int e = idx >> 9;
    int d = idx & (DIM - 1);
    float m = ALPHA_1F * fabsf(W[idx]) / g_deg[e];
    float diag = (e == d) ? 1.f : 0.f;
    if (e == d) m -= (ALPHA_1F + ALPHA_0F + p[d]);
    g_M[idx] = m;
    float g1 = DTF * (m + diag * p[d]);
    g_G[0][idx] = g1;
    g_F[0][idx] = diag + DTF * g1;
}

// ---------------------------------------------------------------------------
// Split-K partial GEMM: g_T[kz] tile = M[:, kz*128:(kz+1)*128] @ F[kz chunk, :]
// grid (8, 8, KS), 256 threads, 64x64 tile, 4x4 per thread, BK=16.
// Software-pipelined global loads (LDG for next tile issued under compute).
// ---------------------------------------------------------------------------
__global__ __launch_bounds__(256)
void step_part(int src) {
    constexpr int BM = 64, BN = 64, BK = 16;
    constexpr int STAGES = KCH / BK;  // 8
    __shared__ float Ms[BK][BM];
    __shared__ float Fs[BK][BN];

    const float* __restrict__ Fsrc = g_F[src];
    float* __restrict__ T = g_T[blockIdx.z];

    const int tid   = threadIdx.x;
    const int brow  = blockIdx.x * BM;
    const int bcol  = blockIdx.y * BN;
    const int kbase = blockIdx.z * KCH;
    const int tx = tid & 15;
    const int ty = tid >> 4;

    // loader lanes
    const int arow = tid >> 2;  // 0..63 (M tile row)
    const int akq  = tid & 3;   // x4 K floats
    const int fkr  = tid >> 4;  // 0..15 (F tile K-row)
    const int fjq  = tid & 15;  // x4 N floats

    float acc[4][4];
    #pragma unroll
    for (int i = 0; i < 4; i++)
        #pragma unroll
        for (int j = 0; j < 4; j++) acc[i][j] = 0.f;

    // prologue loads for stage 0
    float4 avr = *(const float4*)&g_M[(size_t)(brow + arow) * DIM + kbase + akq * 4];
    float4 fvr = *(const float4*)&Fsrc[(size_t)(kbase + fkr) * DIM + bcol + fjq * 4];

    for (int it = 0; it < STAGES; it++) {
        __syncthreads();   // previous compute readers done
        Ms[akq * 4 + 0][arow] = avr.x;
        Ms[akq * 4 + 1][arow] = avr.y;
        Ms[akq * 4 + 2][arow] = avr.z;
        Ms[akq * 4 + 3][arow] = avr.w;
        *(float4*)&Fs[fkr][fjq * 4] = fvr;

        if (it + 1 < STAGES) {
            int k0 = kbase + (it + 1) * BK;
            avr = *(const float4*)&g_M[(size_t)(brow + arow) * DIM + k0 + akq * 4];
            fvr = *(const float4*)&Fsrc[(size_t)(k0 + fkr) * DIM + bcol + fjq * 4];
        }
        __syncthreads();

        #pragma unroll
        for (int kk = 0; kk < BK; kk++) {
            float a[4], b[4];
            #pragma unroll
            for (int i = 0; i < 4; i++) a[i] = Ms[kk][ty * 4 + i];
            #pragma unroll
            for (int j = 0; j < 4; j++) b[j] = Fs[kk][tx * 4 + j];
            #pragma unroll
            for (int i = 0; i < 4; i++)
                #pragma unroll
                for (int j = 0; j < 4; j++)
                    acc[i][j] = fmaf(a[i], b[j], acc[i][j]);
        }
    }

    #pragma unroll
    for (int i = 0; i < 4; i++) {
        int gi = brow + ty * 4 + i;
        float* trow = T + (size_t)gi * DIM + bcol + tx * 4;
        *(float4*)trow = make_float4(acc[i][0], acc[i][1], acc[i][2], acc[i][3]);
    }
}

// ---------------------------------------------------------------------------
// Combine partials + fused step epilogue (float4 over the whole matrix):
//   t = sum_kz T[kz];  G' = c1*G + dt*t (+ dt*p on diag);  F' = F + dt*G'
// ---------------------------------------------------------------------------
__global__ __launch_bounds__(256)
void step_combine(int src, const float* __restrict__ p) {
    int v = blockIdx.x * blockDim.x + threadIdx.x;   // float4 index
    if (v >= DIM * DIM / 4) return;
    int idx = v * 4;
    int gi  = idx >> 9;
    int gj0 = idx & (DIM - 1);

    const float4* __restrict__ T0 = (const float4*)g_T[0];
    const float4* __restrict__ T1 = (const float4*)g_T[1];
    const float4* __restrict__ T2 = (const float4*)g_T[2];
    const float4* __restrict__ T3 = (const float4*)g_T[3];
    const float4* __restrict__ Gs = (const float4*)g_G[src];
    const float4* __restrict__ Fs = (const float4*)g_F[src];
    float4* __restrict__ Gd = (float4*)g_G[src ^ 1];
    float4* __restrict__ Fd = (float4*)g_F[src ^ 1];

    float4 a = T0[v], b = T1[v], c = T2[v], d = T3[v];
    float4 t = make_float4(a.x + b.x + c.x + d.x,
                           a.y + b.y + c.y + d.y,
                           a.z + b.z + c.z + d.z,
                           a.w + b.w + c.w + d.w);
    float4 g = Gs[v], f = Fs[v];

    float pd = (gi >= gj0 && gi < gj0 + 4) ? p[gi] : 0.f;
    float gn[4] = {C1F * g.x + DTF * t.x,
                   C1F * g.y + DTF * t.y,
                   C1F * g.z + DTF * t.z,
                   C1F * g.w + DTF * t.w};
    if (gi >= gj0 && gi < gj0 + 4) gn[gi - gj0] += DTF * pd;

    float4 gv = make_float4(gn[0], gn[1], gn[2], gn[3]);
    float4 fv = make_float4(f.x + DTF * gn[0], f.y + DTF * gn[1],
                            f.z + DTF * gn[2], f.w + DTF * gn[3]);
    Gd[v] = gv;
    Fd[v] = fv;
}

// ---------------------------------------------------------------------------
// H = gate * F_final + (1-gate) * I
// ---------------------------------------------------------------------------
__global__ void finalize_H(const float* __restrict__ ga, int src) {
    int idx = blockIdx.x * blockDim.x + threadIdx.x;
    if (idx >= DIM * DIM) return;
    float gate = tanhf(ga[0]);
    int e = idx >> 9;
    int d = idx & (DIM - 1);
    float v = gate * g_F[src][idx];
    if (e == d) v += 1.0f - gate;
    g_H[idx] = v;
}

// ---------------------------------------------------------------------------
// out[r, e] = sum_d h[r, d] * H[e, d]      (R = B*S = 16384 rows)
// 128x128 tile, 256 threads, 8x8 per thread, BK=16. Both operands K-major.
// ---------------------------------------------------------------------------
__global__ __launch_bounds__(256)
void big_gemm(const float* __restrict__ A, float* __restrict__ C, int R) {
    constexpr int BM = 128, BN = 128, BK = 16;
    __shared__ float As[BK][BM];
    __shared__ float Bs[BK][BN];

    const int tid  = threadIdx.x;
    const int brow = blockIdx.x * BM;
    const int bcol = blockIdx.y * BN;
    const int tx = tid & 15;
    const int ty = tid >> 4;

    float acc[8][8];
    #pragma unroll
    for (int i = 0; i < 8; i++)
        #pragma unroll
        for (int j = 0; j < 8; j++) acc[i][j] = 0.f;

    for (int k0 = 0; k0 < DIM; k0 += BK) {
        #pragma unroll
        for (int t = 0; t < 2; t++) {
            int idx = tid + t * 256;
            int row = idx >> 2;
            int kq  = idx & 3;
            float4 av = *(const float4*)&A[(size_t)(brow + row) * DIM + k0 + kq * 4];
            As[kq * 4 + 0][row] = av.x;
            As[kq * 4 + 1][row] = av.y;
            As[kq * 4 + 2][row] = av.z;
            As[kq * 4 + 3][row] = av.w;
            float4 bv = *(const float4*)&g_H[(size_t)(bcol + row) * DIM + k0 + kq * 4];
            Bs[kq * 4 + 0][row] = bv.x;
            Bs[kq * 4 + 1][row] = bv.y;
            Bs[kq * 4 + 2][row] = bv.z;
            Bs[kq * 4 + 3][row] = bv.w;
        }
        __syncthreads();

        #pragma unroll
        for (int kk = 0; kk < BK; kk++) {
            float a[8], b[8];
            #pragma unroll
            for (int i = 0; i < 8; i++) a[i] = As[kk][ty * 8 + i];
            #pragma unroll
            for (int j = 0; j < 8; j++) b[j] = Bs[kk][tx * 8 + j];
            #pragma unroll
            for (int i = 0; i < 8; i++)
                #pragma unroll
                for (int j = 0; j < 8; j++)
                    acc[i][j] = fmaf(a[i], b[j], acc[i][j]);
        }
        __syncthreads();
    }

    #pragma unroll
    for (int i = 0; i < 8; i++) {
        int r = brow + ty * 8 + i;
        float* crow = C + (size_t)r * DIM + bcol + tx * 8;
        *(float4*)(crow + 0) = make_float4(acc[i][0], acc[i][1], acc[i][2], acc[i][3]);
        *(float4*)(crow + 4) = make_float4(acc[i][4], acc[i][5], acc[i][6], acc[i][7]);
    }
}

// ---------------------------------------------------------------------------
extern "C" void kernel_launch(void* const* d_in, const int* in_sizes, int n_in,
                              void* d_out, int out_size) {
    const float* h  = (const float*)d_in[0];  // hidden_states [B,S,D]
    const float* W  = (const float*)d_in[1];  // [D,D]
    const float* ga = (const float*)d_in[2];  // gate_alpha [1]
    const float* p  = (const float*)d_in[3];  // precision [D]
    float* out = (float*)d_out;

    const int R = in_sizes[0] / DIM;          // B*S = 16384

    build_deg<<<(DIM * 32 + 255) / 256, 256>>>(W);
    build_M_init<<<(DIM * DIM + 255) / 256, 256>>>(W, p);

    int src = 0;
    for (int it = 0; it < 9; it++) {           // steps 2..10 (step 1 analytic)
        step_part<<<dim3(DIM / 64, DIM / 64, KS), 256>>>(src);
        step_combine<<<(DIM * DIM / 4 + 255) / 256, 256>>>(src, p);
        src ^= 1;
    }

    finalize_H<<<(DIM * DIM + 255) / 256, 256>>>(ga, src);

    big_gemm<<<dim3(R / 128, DIM / 128), 256>>>(h, out, R);
}

// round 5
// speedup vs baseline: 1.7611x; 1.1119x over previous
#include <cuda_runtime.h>
#include <math.h>

// ---------------------------------------------------------------------------
// SOMI settling layer — Paterson-Stockmeyer collapsed formulation.
//
//   N = |W|/deg - (1.1 + p) on diag,  deg = max(rowsum|W|, 1e-8)
//   phi_10 = A(N) h + B(N) (p .* h), A deg-10 / B deg-9 polys with scalar
//   coefficients from the 10-step semi-implicit Euler recurrence.
//   H = (1-g)I + g*(D0 + N^4 (D1 + N^4 D2)),  D_j = P_j(N) + Q_j(N) diag(p)
//   out = H @ h (over hidden dim)
//
// 5 GEMMs of 512^3 (split-K) + 1 big GEMM 16384x512x512.
//
// HARD RULE LEARNED R3/R4: never pass a __device__ global symbol as a
// host-side kernel argument (host shadow address + ATS/HMM on the Grace host
// silently migrates pages -> device-memory growth -> harness violation).
// All scratch lives in one arena indexed by small ints passed at launch.
// ---------------------------------------------------------------------------

#define DIM 512
#define KS  8            // split-K slabs for 512^3 GEMMs
#define KCH (DIM / KS)   // 64

// buffer ids in the scratch arena
#define BUF_N   0
#define BUF_N2  1
#define BUF_N3  2
#define BUF_N4  3
#define BUF_D0  4
#define BUF_D1  5
#define BUF_D2  6
#define BUF_E   7
#define BUF_H   8

// Scratch (allocation-free rule: device globals; referenced ONLY in device code)
__device__ __align__(16) float g_deg[DIM];
__device__ __align__(16) float g_buf[9][DIM * DIM];
__device__ __align__(16) float g_T[KS][DIM * DIM];

struct Coef { float P[3][4]; float Q[3][4]; };

// ---------------------------------------------------------------------------
__global__ void build_deg(const float* __restrict__ W) {
    int warp = (blockIdx.x * blockDim.x + threadIdx.x) >> 5;
    int lane = threadIdx.x & 31;
    if (warp >= DIM) return;
    float s = 0.f;
    const float* row = W + (size_t)warp * DIM;
    for (int d = lane; d < DIM; d += 32) s += fabsf(row[d]);
    #pragma unroll
    for (int o = 16; o > 0; o >>= 1) s += __shfl_down_sync(0xffffffffu, s, o);
    if (lane == 0) g_deg[warp] = fmaxf(s, 1e-8f);
}

// N = |W|/deg - (1.1 + p) on diag   (alpha1=1, alpha0=0.1)
__global__ void build_N(const float* __restrict__ W, const float* __restrict__ p) {
    int idx = blockIdx.x * blockDim.x + threadIdx.x;
    if (idx >= DIM * DIM) return;
    int e = idx >> 9;
    int d = idx & (DIM - 1);
    float m = fabsf(W[idx]) / g_deg[e];
    if (e == d) m -= (1.1f + p[d]);
    g_buf[BUF_N][idx] = m;
}

// ---------------------------------------------------------------------------
// Split-K 512^3 GEMM (NN): g_T[z] = A[:, zK:(z+1)K] @ B[zK:(z+1)K, :]
// grid (4, 4, KS), 256 threads, 128x128 tile, 8x8 per thread, BK=16.
// A and B selected by integer arena index (NEVER host-passed symbols).
// ---------------------------------------------------------------------------
__global__ __launch_bounds__(256)
void gemm512(int ai, int bi) {
    constexpr int BM = 128, BN = 128, BK = 16;
    __shared__ float As[BK][BM];
    __shared__ float Bs[BK][BN];

    const float* __restrict__ A = g_buf[ai];
    const float* __restrict__ B = g_buf[bi];
    float* __restrict__ T = g_T[blockIdx.z];

    const int tid   = threadIdx.x;
    const int brow  = blockIdx.x * BM;
    const int bcol  = blockIdx.y * BN;
    const int kbase = blockIdx.z * KCH;
    const int tx = tid & 15;
    const int ty = tid >> 4;

    float acc[8][8];
    #pragma unroll
    for (int i = 0; i < 8; i++)
        #pragma unroll
        for (int j = 0; j < 8; j++) acc[i][j] = 0.f;

    for (int k0 = kbase; k0 < kbase + KCH; k0 += BK) {
        #pragma unroll
        for (int t = 0; t < 2; t++) {
            int idx = tid + t * 256;
            int arow = idx >> 2;
            int akq  = idx & 3;
            float4 av = *(const float4*)&A[(size_t)(brow + arow) * DIM + k0 + akq * 4];
            As[akq * 4 + 0][arow] = av.x;
            As[akq * 4 + 1][arow] = av.y;
            As[akq * 4 + 2][arow] = av.z;
            As[akq * 4 + 3][arow] = av.w;
            int bkr = idx >> 5;
            int bjq = idx & 31;
            float4 bv = *(const float4*)&B[(size_t)(k0 + bkr) * DIM + bcol + bjq * 4];
            *(float4*)&Bs[bkr][bjq * 4] = bv;
        }
        __syncthreads();

        #pragma unroll
        for (int kk = 0; kk < BK; kk++) {
            float a[8], b[8];
            #pragma unroll
            for (int i = 0; i < 8; i++) a[i] = As[kk][ty * 8 + i];
            #pragma unroll
            for (int j = 0; j < 8; j++) b[j] = Bs[kk][tx * 8 + j];
            #pragma unroll
            for (int i = 0; i < 8; i++)
                #pragma unroll
                for (int j = 0; j < 8; j++)
                    acc[i][j] = fmaf(a[i], b[j], acc[i][j]);
        }
        __syncthreads();
    }

    #pragma unroll
    for (int i = 0; i < 8; i++) {
        float* trow = T + (size_t)(brow + ty * 8 + i) * DIM + bcol + tx * 8;
        *(float4*)(trow + 0) = make_float4(acc[i][0], acc[i][1], acc[i][2], acc[i][3]);
        *(float4*)(trow + 4) = make_float4(acc[i][4], acc[i][5], acc[i][6], acc[i][7]);
    }
}

// ---------------------------------------------------------------------------
// Combine variants (sum KS partial slabs, optional epilogues). float4 grain.
// ---------------------------------------------------------------------------
__device__ __forceinline__ float4 slab_sum(int v) {
    float4 s = ((const float4*)g_T[0])[v];
    #pragma unroll
    for (int z = 1; z < KS; z++) {
        float4 t = ((const float4*)g_T[z])[v];
        s.x += t.x; s.y += t.y; s.z += t.z; s.w += t.w;
    }
    return s;
}

__global__ __launch_bounds__(256)
void combine_sum(int di) {
    int v = blockIdx.x * blockDim.x + threadIdx.x;
    if (v >= DIM * DIM / 4) return;
    ((float4*)g_buf[di])[v] = slab_sum(v);
}

__global__ __launch_bounds__(256)
void combine_add(int di, int addi) {
    int v = blockIdx.x * blockDim.x + threadIdx.x;
    if (v >= DIM * DIM / 4) return;
    float4 s = slab_sum(v);
    float4 a = ((const float4*)g_buf[addi])[v];
    ((float4*)g_buf[di])[v] = make_float4(s.x + a.x, s.y + a.y, s.z + a.z, s.w + a.w);
}

// H = g*(sum + D0) + (1-g) I   (branchless diagonal add)
__global__ __launch_bounds__(256)
void combine_H(const float* __restrict__ ga) {
    int v = blockIdx.x * blockDim.x + threadIdx.x;
    if (v >= DIM * DIM / 4) return;
    float g = tanhf(ga[0]);
    float4 s = slab_sum(v);
    float4 a = ((const float4*)g_buf[BUF_D0])[v];
    int idx = v * 4;
    int gi  = idx >> 9;
    int gj0 = idx & (DIM - 1);
    float omg = 1.0f - g;
    float r0 = g * (s.x + a.x) + ((gi == gj0 + 0) ? omg : 0.f);
    float r1 = g * (s.y + a.y) + ((gi == gj0 + 1) ? omg : 0.f);
    float r2 = g * (s.z + a.z) + ((gi == gj0 + 2) ? omg : 0.f);
    float r3 = g * (s.w + a.w) + ((gi == gj0 + 3) ? omg : 0.f);
    ((float4*)g_buf[BUF_H])[v] = make_float4(r0, r1, r2, r3);
}

// ---------------------------------------------------------------------------
// D_j = P_j(N) + Q_j(N) * diag(p)  — fully explicit
// ---------------------------------------------------------------------------
__global__ __launch_bounds__(256)
void build_D(const float* __restrict__ p, Coef cf) {
    int idx = blockIdx.x * blockDim.x + threadIdx.x;
    if (idx >= DIM * DIM) return;
    int e = idx >> 9;
    int d = idx & (DIM - 1);
    float x0 = (e == d) ? 1.f : 0.f;
    float x1 = g_buf[BUF_N ][idx];
    float x2 = g_buf[BUF_N2][idx];
    float x3 = g_buf[BUF_N3][idx];
    float pd = p[d];

    float vp0 = cf.P[0][0] * x0 + cf.P[0][1] * x1 + cf.P[0][2] * x2 + cf.P[0][3] * x3;
    float vq0 = cf.Q[0][0] * x0 + cf.Q[0][1] * x1 + cf.Q[0][2] * x2 + cf.Q[0][3] * x3;
    g_buf[BUF_D0][idx] = vp0 + vq0 * pd;

    float vp1 = cf.P[1][0] * x0 + cf.P[1][1] * x1 + cf.P[1][2] * x2 + cf.P[1][3] * x3;
    float vq1 = cf.Q[1][0] * x0 + cf.Q[1][1] * x1 + cf.Q[1][2] * x2 + cf.Q[1][3] * x3;
    g_buf[BUF_D1][idx] = vp1 + vq1 * pd;

    float vp2 = cf.P[2][0] * x0 + cf.P[2][1] * x1 + cf.P[2][2] * x2 + cf.P[2][3] * x3;
    float vq2 = cf.Q[2][0] * x0 + cf.Q[2][1] * x1 + cf.Q[2][2] * x2 + cf.Q[2][3] * x3;
    g_buf[BUF_D2][idx] = vp2 + vq2 * pd;
}

// ---------------------------------------------------------------------------
// out[r, e] = sum_d h[r, d] * H[e, d]      (R = B*S = 16384 rows)
// (H read from arena internally — same pattern that passed in round 2)
// ---------------------------------------------------------------------------
__global__ __launch_bounds__(256)
void big_gemm(const float* __restrict__ A, float* __restrict__ C, int R) {
    constexpr int BM = 128, BN = 128, BK = 16;
    __shared__ float As[BK][BM];
    __shared__ float Bs[BK][BN];

    const float* __restrict__ Hm = g_buf[BUF_H];
    const int tid  = threadIdx.x;
    const int brow = blockIdx.x * BM;
    const int bcol = blockIdx.y * BN;
    const int tx = tid & 15;
    const int ty = tid >> 4;

    float acc[8][8];
    #pragma unroll
    for (int i = 0; i < 8; i++)
        #pragma unroll
        for (int j = 0; j < 8; j++) acc[i][j] = 0.f;

    for (int k0 = 0; k0 < DIM; k0 += BK) {
        #pragma unroll
        for (int t = 0; t < 2; t++) {
            int idx = tid + t * 256;
            int row = idx >> 2;
            int kq  = idx & 3;
            float4 av = *(const float4*)&A[(size_t)(brow + row) * DIM + k0 + kq * 4];
            As[kq * 4 + 0][row] = av.x;
            As[kq * 4 + 1][row] = av.y;
            As[kq * 4 + 2][row] = av.z;
            As[kq * 4 + 3][row] = av.w;
            float4 bv = *(const float4*)&Hm[(size_t)(bcol + row) * DIM + k0 + kq * 4];
            Bs[kq * 4 + 0][row] = bv.x;
            Bs[kq * 4 + 1][row] = bv.y;
            Bs[kq * 4 + 2][row] = bv.z;
            Bs[kq * 4 + 3][row] = bv.w;
        }
        __syncthreads();

        #pragma unroll
        for (int kk = 0; kk < BK; kk++) {
            float a[8], b[8];
            #pragma unroll
            for (int i = 0; i < 8; i++) a[i] = As[kk][ty * 8 + i];
            #pragma unroll
            for (int j = 0; j < 8; j++) b[j] = Bs[kk][tx * 8 + j];
            #pragma unroll
            for (int i = 0; i < 8; i++)
                #pragma unroll
                for (int j = 0; j < 8; j++)
                    acc[i][j] = fmaf(a[i], b[j], acc[i][j]);
        }
        __syncthreads();
    }

    #pragma unroll
    for (int i = 0; i < 8; i++) {
        int r = brow + ty * 8 + i;
        float* crow = C + (size_t)r * DIM + bcol + tx * 8;
        *(float4*)(crow + 0) = make_float4(acc[i][0], acc[i][1], acc[i][2], acc[i][3]);
        *(float4*)(crow + 4) = make_float4(acc[i][4], acc[i][5], acc[i][6], acc[i][7]);
    }
}

// ---------------------------------------------------------------------------
extern "C" void kernel_launch(void* const* d_in, const int* in_sizes, int n_in,
                              void* d_out, int out_size) {
    const float* h  = (const float*)d_in[0];  // hidden_states [B,S,D]
    const float* W  = (const float*)d_in[1];  // [D,D]
    const float* ga = (const float*)d_in[2];  // gate_alpha [1]
    const float* p  = (const float*)d_in[3];  // precision [D]
    float* out = (float*)d_out;

    const int R = in_sizes[0] / DIM;          // B*S = 16384

    // ---- host-side polynomial coefficients (doubles; deterministic) ----
    // v' = c1 v + dt N phi + dt u;  phi' = phi + dt v'   (u = p .* h, phi0 = h)
    // phi_n = A_n(N) h + B_n(N) u
    double Ac[12] = {0}, Bc[12] = {0}, Cc[12] = {0}, Dc[12] = {0};
    Ac[0] = 1.0;
    {
        const double dt = 0.1, beta = 2.0 * sqrt(2.1), c1 = 1.0 - dt * beta;
        for (int n = 0; n < 10; n++) {
            double Cn[12], Dn[12];
            for (int k = 0; k < 12; k++) {
                Cn[k] = c1 * Cc[k] + (k > 0 ? dt * Ac[k - 1] : 0.0);
                Dn[k] = c1 * Dc[k] + (k > 0 ? dt * Bc[k - 1] : 0.0);
            }
            Dn[0] += dt;
            for (int k = 0; k < 12; k++) {
                Cc[k] = Cn[k];  Dc[k] = Dn[k];
                Ac[k] += dt * Cn[k];
                Bc[k] += dt * Dn[k];
            }
        }
    }
    Coef cf;
    for (int j = 0; j < 3; j++)
        for (int m = 0; m < 4; m++) {
            cf.P[j][m] = (float)Ac[4 * j + m];
            cf.Q[j][m] = (float)Bc[4 * j + m];
        }

    const int NELT_BLKS = (DIM * DIM + 255) / 256;
    const int VEC_BLKS  = (DIM * DIM / 4 + 255) / 256;
    const dim3 GG(4, 4, KS);

    build_deg<<<(DIM * 32 + 255) / 256, 256>>>(W);
    build_N<<<NELT_BLKS, 256>>>(W, p);

    gemm512<<<GG, 256>>>(BUF_N, BUF_N);        // N^2
    combine_sum<<<VEC_BLKS, 256>>>(BUF_N2);
    gemm512<<<GG, 256>>>(BUF_N, BUF_N2);       // N^3
    combine_sum<<<VEC_BLKS, 256>>>(BUF_N3);
    gemm512<<<GG, 256>>>(BUF_N2, BUF_N2);      // N^4
    combine_sum<<<VEC_BLKS, 256>>>(BUF_N4);

    build_D<<<NELT_BLKS, 256>>>(p, cf);

    gemm512<<<GG, 256>>>(BUF_N4, BUF_D2);      // E = N^4 D2 + D1
    combine_add<<<VEC_BLKS, 256>>>(BUF_E, BUF_D1);
    gemm512<<<GG, 256>>>(BUF_N4, BUF_E);       // H = g*(N^4 E + D0) + (1-g)I
    combine_H<<<VEC_BLKS, 256>>>(ga);

    big_gemm<<<dim3(R / 128, DIM / 128), 256>>>(h, out, R);
}

// round 7
// speedup vs baseline: 2.8083x; 1.5946x over previous
#include <cuda_runtime.h>
#include <cuda_bf16.h>
#include <math.h>
#include <cstdint>

// ---------------------------------------------------------------------------
// SOMI settling layer — Paterson-Stockmeyer collapsed formulation.
//   N = |W|/deg - (1.1 + p) on diag;  H = (1-g)I + g*(D0 + N^4(D1 + N^4 D2))
//   out = H @ h over the hidden dim.
// Poly chain: 5x 512^3 fp32 SIMT GEMMs (split-K).  Final apply: warp-level
// mma.sync bf16 hi/lo split GEMM (hi*hi + hi*lo + lo*hi, fp32 accumulate).
//
// HARD RULES LEARNED:
//  R3/R4: never pass __device__ global symbols as host-side kernel args
//         (Grace ATS migrates pages -> harness allocation violation).
//  R6:    harness compiles to baseline sm_100 (NOT sm_100a) -> tcgen05/TMEM
//         PTX is rejected by ptxas. Only baseline ISA: mma.sync + ldmatrix.
// ---------------------------------------------------------------------------

#define DIM 512
#define KS  8
#define KCH (DIM / KS)

#define BUF_N   0
#define BUF_N2  1
#define BUF_N3  2
#define BUF_N4  3
#define BUF_D0  4
#define BUF_D1  5
#define BUF_D2  6
#define BUF_E   7

__device__ __align__(16) float g_deg[DIM];
__device__ __align__(16) float g_buf[8][DIM * DIM];
__device__ __align__(16) float g_T[KS][DIM * DIM];
__device__ __align__(16) __nv_bfloat16 g_Hhi[DIM * DIM];
__device__ __align__(16) __nv_bfloat16 g_Hlo[DIM * DIM];

struct Coef { float P[3][4]; float Q[3][4]; };

// ======================= helpers ===========================================
__device__ __forceinline__ uint32_t smem_u32(const void* p) {
    uint32_t a;
    asm("{ .reg .u64 t; cvta.to.shared.u64 t, %1; cvt.u32.u64 %0, t; }"
        : "=r"(a) : "l"(p));
    return a;
}
__device__ __forceinline__ uint32_t bf2_pack(__nv_bfloat16 a, __nv_bfloat16 b) {
    __nv_bfloat162 t = __halves2bfloat162(a, b);
    return *reinterpret_cast<uint32_t*>(&t);
}
__device__ __forceinline__ void ldm_x4(uint32_t& r0, uint32_t& r1,
                                       uint32_t& r2, uint32_t& r3, uint32_t a) {
    asm volatile("ldmatrix.sync.aligned.m8n8.x4.shared.b16 {%0,%1,%2,%3}, [%4];"
                 : "=r"(r0), "=r"(r1), "=r"(r2), "=r"(r3) : "r"(a));
}
__device__ __forceinline__ void ldm_x2(uint32_t& r0, uint32_t& r1, uint32_t a) {
    asm volatile("ldmatrix.sync.aligned.m8n8.x2.shared.b16 {%0,%1}, [%2];"
                 : "=r"(r0), "=r"(r1) : "r"(a));
}
__device__ __forceinline__ void mma_bf16(float* c, const uint32_t* a,
                                         const uint32_t* b) {
    asm volatile(
        "mma.sync.aligned.m16n8k16.row.col.f32.bf16.bf16.f32 "
        "{%0,%1,%2,%3}, {%4,%5,%6,%7}, {%8,%9}, {%0,%1,%2,%3};"
        : "+f"(c[0]), "+f"(c[1]), "+f"(c[2]), "+f"(c[3])
        : "r"(a[0]), "r"(a[1]), "r"(a[2]), "r"(a[3]), "r"(b[0]), "r"(b[1]));
}

// ======================= pre/poly kernels (unchanged, proven) ==============
__global__ void build_deg(const float* __restrict__ W) {
    int warp = (blockIdx.x * blockDim.x + threadIdx.x) >> 5;
    int lane = threadIdx.x & 31;
    if (warp >= DIM) return;
    float s = 0.f;
    const float* row = W + (size_t)warp * DIM;
    for (int d = lane; d < DIM; d += 32) s += fabsf(row[d]);
    #pragma unroll
    for (int o = 16; o > 0; o >>= 1) s += __shfl_down_sync(0xffffffffu, s, o);
    if (lane == 0) g_deg[warp] = fmaxf(s, 1e-8f);
}

__global__ void build_N(const float* __restrict__ W, const float* __restrict__ p) {
    int idx = blockIdx.x * blockDim.x + threadIdx.x;
    if (idx >= DIM * DIM) return;
    int e = idx >> 9;
    int d = idx & (DIM - 1);
    float m = fabsf(W[idx]) / g_deg[e];
    if (e == d) m -= (1.1f + p[d]);
    g_buf[BUF_N][idx] = m;
}

__global__ __launch_bounds__(256)
void gemm512(int ai, int bi) {
    constexpr int BM = 128, BN = 128, BK = 16;
    __shared__ float As[BK][BM];
    __shared__ float Bs[BK][BN];

    const float* __restrict__ A = g_buf[ai];
    const float* __restrict__ B = g_buf[bi];
    float* __restrict__ T = g_T[blockIdx.z];

    const int tid   = threadIdx.x;
    const int brow  = blockIdx.x * BM;
    const int bcol  = blockIdx.y * BN;
    const int kbase = blockIdx.z * KCH;
    const int tx = tid & 15;
    const int ty = tid >> 4;

    float acc[8][8];
    #pragma unroll
    for (int i = 0; i < 8; i++)
        #pragma unroll
        for (int j = 0; j < 8; j++) acc[i][j] = 0.f;

    for (int k0 = kbase; k0 < kbase + KCH; k0 += BK) {
        #pragma unroll
        for (int t = 0; t < 2; t++) {
            int idx = tid + t * 256;
            int arow = idx >> 2;
            int akq  = idx & 3;
            float4 av = *(const float4*)&A[(size_t)(brow + arow) * DIM + k0 + akq * 4];
            As[akq * 4 + 0][arow] = av.x;
            As[akq * 4 + 1][arow] = av.y;
            As[akq * 4 + 2][arow] = av.z;
            As[akq * 4 + 3][arow] = av.w;
            int bkr = idx >> 5;
            int bjq = idx & 31;
            float4 bv = *(const float4*)&B[(size_t)(k0 + bkr) * DIM + bcol + bjq * 4];
            *(float4*)&Bs[bkr][bjq * 4] = bv;
        }
        __syncthreads();

        #pragma unroll
        for (int kk = 0; kk < BK; kk++) {
            float a[8], b[8];
            #pragma unroll
            for (int i = 0; i < 8; i++) a[i] = As[kk][ty * 8 + i];
            #pragma unroll
            for (int j = 0; j < 8; j++) b[j] = Bs[kk][tx * 8 + j];
            #pragma unroll
            for (int i = 0; i < 8; i++)
                #pragma unroll
                for (int j = 0; j < 8; j++)
                    acc[i][j] = fmaf(a[i], b[j], acc[i][j]);
        }
        __syncthreads();
    }

    #pragma unroll
    for (int i = 0; i < 8; i++) {
        float* trow = T + (size_t)(brow + ty * 8 + i) * DIM + bcol + tx * 8;
        *(float4*)(trow + 0) = make_float4(acc[i][0], acc[i][1], acc[i][2], acc[i][3]);
        *(float4*)(trow + 4) = make_float4(acc[i][4], acc[i][5], acc[i][6], acc[i][7]);
    }
}

__device__ __forceinline__ float4 slab_sum(int v) {
    float4 s = ((const float4*)g_T[0])[v];
    #pragma unroll
    for (int z = 1; z < KS; z++) {
        float4 t = ((const float4*)g_T[z])[v];
        s.x += t.x; s.y += t.y; s.z += t.z; s.w += t.w;
    }
    return s;
}

__global__ __launch_bounds__(256)
void combine_sum(int di) {
    int v = blockIdx.x * blockDim.x + threadIdx.x;
    if (v >= DIM * DIM / 4) return;
    ((float4*)g_buf[di])[v] = slab_sum(v);
}

__global__ __launch_bounds__(256)
void combine_add(int di, int addi) {
    int v = blockIdx.x * blockDim.x + threadIdx.x;
    if (v >= DIM * DIM / 4) return;
    float4 s = slab_sum(v);
    float4 a = ((const float4*)g_buf[addi])[v];
    ((float4*)g_buf[di])[v] = make_float4(s.x + a.x, s.y + a.y, s.z + a.z, s.w + a.w);
}

// H = g*(sum + D0) + (1-g) I  -> split into bf16 hi/lo for the mma GEMM
__global__ __launch_bounds__(256)
void combine_H(const float* __restrict__ ga) {
    int v = blockIdx.x * blockDim.x + threadIdx.x;
    if (v >= DIM * DIM / 4) return;
    float g = tanhf(ga[0]);
    float4 s = slab_sum(v);
    float4 a = ((const float4*)g_buf[BUF_D0])[v];
    int idx = v * 4;
    int gi  = idx >> 9;
    int gj0 = idx & (DIM - 1);
    float omg = 1.0f - g;
    float r0 = g * (s.x + a.x) + ((gi == gj0 + 0) ? omg : 0.f);
    float r1 = g * (s.y + a.y) + ((gi == gj0 + 1) ? omg : 0.f);
    float r2 = g * (s.z + a.z) + ((gi == gj0 + 2) ? omg : 0.f);
    float r3 = g * (s.w + a.w) + ((gi == gj0 + 3) ? omg : 0.f);

    __nv_bfloat16 h0 = __float2bfloat16_rn(r0);
    __nv_bfloat16 h1 = __float2bfloat16_rn(r1);
    __nv_bfloat16 h2 = __float2bfloat16_rn(r2);
    __nv_bfloat16 h3 = __float2bfloat16_rn(r3);
    __nv_bfloat16 l0 = __float2bfloat16_rn(r0 - __bfloat162float(h0));
    __nv_bfloat16 l1 = __float2bfloat16_rn(r1 - __bfloat162float(h1));
    __nv_bfloat16 l2 = __float2bfloat16_rn(r2 - __bfloat162float(h2));
    __nv_bfloat16 l3 = __float2bfloat16_rn(r3 - __bfloat162float(h3));
    *(uint2*)&g_Hhi[idx] = make_uint2(bf2_pack(h0, h1), bf2_pack(h2, h3));
    *(uint2*)&g_Hlo[idx] = make_uint2(bf2_pack(l0, l1), bf2_pack(l2, l3));
}

__global__ __launch_bounds__(256)
void build_D(const float* __restrict__ p, Coef cf) {
    int idx = blockIdx.x * blockDim.x + threadIdx.x;
    if (idx >= DIM * DIM) return;
    int e = idx >> 9;
    int d = idx & (DIM - 1);
    float x0 = (e == d) ? 1.f : 0.f;
    float x1 = g_buf[BUF_N ][idx];
    float x2 = g_buf[BUF_N2][idx];
    float x3 = g_buf[BUF_N3][idx];
    float pd = p[d];

    float vp0 = cf.P[0][0] * x0 + cf.P[0][1] * x1 + cf.P[0][2] * x2 + cf.P[0][3] * x3;
    float vq0 = cf.Q[0][0] * x0 + cf.Q[0][1] * x1 + cf.Q[0][2] * x2 + cf.Q[0][3] * x3;
    g_buf[BUF_D0][idx] = vp0 + vq0 * pd;

    float vp1 = cf.P[1][0] * x0 + cf.P[1][1] * x1 + cf.P[1][2] * x2 + cf.P[1][3] * x3;
    float vq1 = cf.Q[1][0] * x0 + cf.Q[1][1] * x1 + cf.Q[1][2] * x2 + cf.Q[1][3] * x3;
    g_buf[BUF_D1][idx] = vp1 + vq1 * pd;

    float vp2 = cf.P[2][0] * x0 + cf.P[2][1] * x1 + cf.P[2][2] * x2 + cf.P[2][3] * x3;
    float vq2 = cf.Q[2][0] * x0 + cf.Q[2][1] * x1 + cf.Q[2][2] * x2 + cf.Q[2][3] * x3;
    g_buf[BUF_D2][idx] = vp2 + vq2 * pd;
}

// ======================= mma.sync big GEMM =================================
// out[r, e] = sum_d h[r, d] * H[e, d]
// CTA tile 128x128, 8 warps (2 m-halves x 4 n-quarters), warp tile 64x32.
// K chunks of 32 bf16; per k-step (16): m16n8k16 mma, 3 split products.
// SMEM rows padded to 40 bf16 (80 B) -> ldmatrix bank-conflict-free.
#define APAD 40

__global__ __launch_bounds__(256, 1)
void mma_gemm(const float* __restrict__ h, float* __restrict__ out) {
    __shared__ __align__(16) uint16_t Ahi[128][APAD];
    __shared__ __align__(16) uint16_t Alo[128][APAD];
    __shared__ __align__(16) uint16_t Bhi[128][APAD];
    __shared__ __align__(16) uint16_t Blo[128][APAD];

    const int tid  = threadIdx.x;
    const int wid  = tid >> 5;
    const int lane = tid & 31;
    const int wr = wid & 1;        // m-half (64 rows)
    const int wc = wid >> 1;       // n-quarter (32 cols)
    const int brow = blockIdx.x * 128;
    const int bcol = blockIdx.y * 128;

    float acc[4][4][4];            // [mtile][ntile][frag]
    #pragma unroll
    for (int i = 0; i < 4; i++)
        #pragma unroll
        for (int j = 0; j < 4; j++)
            #pragma unroll
            for (int q = 0; q < 4; q++) acc[i][j][q] = 0.f;

    // precomputed ldmatrix smem addresses (per lane, advance by k within loop)
    const uint32_t aBase = smem_u32(&Ahi[0][0]);
    const uint32_t alBase = smem_u32(&Alo[0][0]);
    const uint32_t bBase = smem_u32(&Bhi[0][0]);
    const uint32_t blBase = smem_u32(&Blo[0][0]);
    const int aRow = wr * 64 + (lane & 15);       // + mt*16
    const int aKp  = (lane >> 4) * 8;             // + kk
    const int bRow = wc * 32 + (lane & 7);        // + nt*8
    const int bKp  = ((lane >> 3) & 1) * 8;       // + kk

    for (int ch = 0; ch < 16; ch++) {
        const int k0 = ch * 32;

        // --- A: 128 rows x 32 K fp32 -> bf16 hi/lo (1024 float4; 4/thread)
        #pragma unroll
        for (int i = 0; i < 4; i++) {
            int t = tid + i * 256;
            int row = t >> 3;
            int q   = t & 7;
            float4 v = *(const float4*)&h[(size_t)(brow + row) * DIM + k0 + q * 4];
            __nv_bfloat16 hx = __float2bfloat16_rn(v.x);
            __nv_bfloat16 hy = __float2bfloat16_rn(v.y);
            __nv_bfloat16 hz = __float2bfloat16_rn(v.z);
            __nv_bfloat16 hw = __float2bfloat16_rn(v.w);
            __nv_bfloat16 lx = __float2bfloat16_rn(v.x - __bfloat162float(hx));
            __nv_bfloat16 ly = __float2bfloat16_rn(v.y - __bfloat162float(hy));
            __nv_bfloat16 lz = __float2bfloat16_rn(v.z - __bfloat162float(hz));
            __nv_bfloat16 lw = __float2bfloat16_rn(v.w - __bfloat162float(hw));
            *(uint2*)&Ahi[row][q * 4] = make_uint2(bf2_pack(hx, hy), bf2_pack(hz, hw));
            *(uint2*)&Alo[row][q * 4] = make_uint2(bf2_pack(lx, ly), bf2_pack(lz, lw));
        }
        // --- B: 128 rows x 32 K bf16 hi/lo direct (512 uint4; 2/thread each)
        #pragma unroll
        for (int i = 0; i < 2; i++) {
            int t = tid + i * 256;
            int row = t >> 2;
            int q   = t & 3;
            uint4 bh = *(const uint4*)&g_Hhi[(size_t)(bcol + row) * DIM + k0 + q * 8];
            *(uint4*)&Bhi[row][q * 8] = bh;
            uint4 bl = *(const uint4*)&g_Hlo[(size_t)(bcol + row) * DIM + k0 + q * 8];
            *(uint4*)&Blo[row][q * 8] = bl;
        }
        __syncthreads();

        #pragma unroll
        for (int ks = 0; ks < 2; ks++) {
            const int kk = ks * 16;
            uint32_t ah[4][4], al[4][4], bh[4][2], bl[4][2];
            #pragma unroll
            for (int mt = 0; mt < 4; mt++) {
                uint32_t ao = ((uint32_t)((aRow + mt * 16) * APAD + kk + aKp)) * 2;
                ldm_x4(ah[mt][0], ah[mt][1], ah[mt][2], ah[mt][3], aBase + ao);
                ldm_x4(al[mt][0], al[mt][1], al[mt][2], al[mt][3], alBase + ao);
            }
            #pragma unroll
            for (int nt = 0; nt < 4; nt++) {
                uint32_t bo = ((uint32_t)((bRow + nt * 8) * APAD + kk + bKp)) * 2;
                ldm_x2(bh[nt][0], bh[nt][1], bBase + bo);
                ldm_x2(bl[nt][0], bl[nt][1], blBase + bo);
            }
            #pragma unroll
            for (int mt = 0; mt < 4; mt++)
                #pragma unroll
                for (int nt = 0; nt < 4; nt++) {
                    mma_bf16(acc[mt][nt], ah[mt], bh[nt]);
                    mma_bf16(acc[mt][nt], ah[mt], bl[nt]);
                    mma_bf16(acc[mt][nt], al[mt], bh[nt]);
                }
        }
        __syncthreads();
    }

    // Epilogue: standard m16n8k16 D layout; 8B stores
    const int er = brow + wr * 64 + (lane >> 2);
    const int ec = bcol + wc * 32 + (lane & 3) * 2;
    #pragma unroll
    for (int mt = 0; mt < 4; mt++) {
        #pragma unroll
        for (int nt = 0; nt < 4; nt++) {
            float* p0 = out + (size_t)(er + mt * 16) * DIM + ec + nt * 8;
            *(float2*)p0 = make_float2(acc[mt][nt][0], acc[mt][nt][1]);
            float* p1 = out + (size_t)(er + mt * 16 + 8) * DIM + ec + nt * 8;
            *(float2*)p1 = make_float2(acc[mt][nt][2], acc[mt][nt][3]);
        }
    }
}

// ---------------------------------------------------------------------------
extern "C" void kernel_launch(void* const* d_in, const int* in_sizes, int n_in,
                              void* d_out, int out_size) {
    const float* h  = (const float*)d_in[0];  // hidden_states [B,S,D]
    const float* W  = (const float*)d_in[1];  // [D,D]
    const float* ga = (const float*)d_in[2];  // gate_alpha [1]
    const float* p  = (const float*)d_in[3];  // precision [D]
    float* out = (float*)d_out;

    const int R = in_sizes[0] / DIM;          // B*S = 16384

    // host-side polynomial coefficients (doubles; deterministic)
    double Ac[12] = {0}, Bc[12] = {0}, Cc[12] = {0}, Dc[12] = {0};
    Ac[0] = 1.0;
    {
        const double dt = 0.1, beta = 2.0 * sqrt(2.1), c1 = 1.0 - dt * beta;
        for (int n = 0; n < 10; n++) {
            double Cn[12], Dn[12];
            for (int k = 0; k < 12; k++) {
                Cn[k] = c1 * Cc[k] + (k > 0 ? dt * Ac[k - 1] : 0.0);
                Dn[k] = c1 * Dc[k] + (k > 0 ? dt * Bc[k - 1] : 0.0);
            }
            Dn[0] += dt;
            for (int k = 0; k < 12; k++) {
                Cc[k] = Cn[k];  Dc[k] = Dn[k];
                Ac[k] += dt * Cn[k];
                Bc[k] += dt * Dn[k];
            }
        }
    }
    Coef cf;
    for (int j = 0; j < 3; j++)
        for (int m = 0; m < 4; m++) {
            cf.P[j][m] = (float)Ac[4 * j + m];
            cf.Q[j][m] = (float)Bc[4 * j + m];
        }

    const int NELT_BLKS = (DIM * DIM + 255) / 256;
    const int VEC_BLKS  = (DIM * DIM / 4 + 255) / 256;
    const dim3 GG(4, 4, KS);

    build_deg<<<(DIM * 32 + 255) / 256, 256>>>(W);
    build_N<<<NELT_BLKS, 256>>>(W, p);

    gemm512<<<GG, 256>>>(BUF_N, BUF_N);        // N^2
    combine_sum<<<VEC_BLKS, 256>>>(BUF_N2);
    gemm512<<<GG, 256>>>(BUF_N, BUF_N2);       // N^3
    combine_sum<<<VEC_BLKS, 256>>>(BUF_N3);
    gemm512<<<GG, 256>>>(BUF_N2, BUF_N2);      // N^4
    combine_sum<<<VEC_BLKS, 256>>>(BUF_N4);

    build_D<<<NELT_BLKS, 256>>>(p, cf);

    gemm512<<<GG, 256>>>(BUF_N4, BUF_D2);      // E = N^4 D2 + D1
    combine_add<<<VEC_BLKS, 256>>>(BUF_E, BUF_D1);
    gemm512<<<GG, 256>>>(BUF_N4, BUF_E);       // H = g*(N^4 E + D0) + (1-g)I
    combine_H<<<VEC_BLKS, 256>>>(ga);

    mma_gemm<<<dim3(R / 128, DIM / 128), 256>>>(h, out);
}